// round 11
// baseline (speedup 1.0000x reference)
#include <cuda_runtime.h>
#include <cstdint>

// PPRGo: out[n,:] = sum_k ( mask(wei[n,k]) / (sum_k mask + 1e-12) ) * emb_table[nei[n,k], :]
// N=200000, TOPK=32, EMB=64. nei is int32 on the wire.
//
// FINAL family (R4 config: 88.8us best, reproduced 90.3us). One warp per
// node; LDG.128 covers TWO neighbor rows per instruction (lanes 0-15 ->
// row 2j, lanes 16-31 -> row 2j+1), default register budget (32 regs,
// ~88% occupancy) — at the L1tex wavefront floor (~128 phases/node).
// R11 micro-opt: weight-sum via popc(ballot) (2 ops) instead of the 5-step
// shfl_xor+FADD tree (10 ops). Inner-loop weight broadcasts unchanged
// (R7 showed replacing THOSE with bit-tests regresses). s is bit-identical.
// Closed axes: cache hints (R3/R8), high-MLP via regs (R5/R6), full ballot
// weights (R7), TMA staging (R9).

static constexpr int TOPK = 32;
static constexpr int EMB  = 64;

__global__ __launch_bounds__(256)
void pprgo_kernel(const float* __restrict__ emb,   // [N, 64]
                  const float* __restrict__ wei,   // [N, 32]
                  const int*   __restrict__ nei,   // [N, 32] int32
                  float* __restrict__ out,         // [N, 64]
                  int n_nodes)
{
    const int warp_id = (blockIdx.x * blockDim.x + threadIdx.x) >> 5;
    const int lane    = threadIdx.x & 31;
    if (warp_id >= n_nodes) return;

    const size_t row = (size_t)warp_id * TOPK;

    // --- weight phase: lane k handles neighbor k ---
    float w = wei[row + lane];
    const bool nz = (w != 0.0f);
    const unsigned ballot = __ballot_sync(0xFFFFFFFFu, nz);
    const float s = (float)__popc(ballot);              // bit-identical to shfl tree
    const float myw = (nz ? 1.0f : 0.0f) * (1.0f / (s + 1e-12f));

    const int myidx = nei[row + lane];

    // --- gather phase: half-warp h owns row 2j+h; lane covers 4 floats ---
    const int half = lane >> 4;          // 0 or 1
    const int hl   = lane & 15;          // position within half-warp

    const float4* __restrict__ e4 = reinterpret_cast<const float4*>(emb);

    float4 acc = make_float4(0.f, 0.f, 0.f, 0.f);

    #pragma unroll
    for (int j = 0; j < TOPK / 2; j += 8) {
        int src0 = 2 * (j + 0) + half;
        int src1 = 2 * (j + 1) + half;
        int src2 = 2 * (j + 2) + half;
        int src3 = 2 * (j + 3) + half;
        int src4 = 2 * (j + 4) + half;
        int src5 = 2 * (j + 5) + half;
        int src6 = 2 * (j + 6) + half;
        int src7 = 2 * (j + 7) + half;

        // 32-bit element offsets: max index 200000*16+15 < 2^32
        unsigned o0 = (unsigned)__shfl_sync(0xFFFFFFFFu, myidx, src0) * (EMB/4) + hl;
        unsigned o1 = (unsigned)__shfl_sync(0xFFFFFFFFu, myidx, src1) * (EMB/4) + hl;
        unsigned o2 = (unsigned)__shfl_sync(0xFFFFFFFFu, myidx, src2) * (EMB/4) + hl;
        unsigned o3 = (unsigned)__shfl_sync(0xFFFFFFFFu, myidx, src3) * (EMB/4) + hl;
        unsigned o4 = (unsigned)__shfl_sync(0xFFFFFFFFu, myidx, src4) * (EMB/4) + hl;
        unsigned o5 = (unsigned)__shfl_sync(0xFFFFFFFFu, myidx, src5) * (EMB/4) + hl;
        unsigned o6 = (unsigned)__shfl_sync(0xFFFFFFFFu, myidx, src6) * (EMB/4) + hl;
        unsigned o7 = (unsigned)__shfl_sync(0xFFFFFFFFu, myidx, src7) * (EMB/4) + hl;

        float w0 = __shfl_sync(0xFFFFFFFFu, myw, src0);
        float w1 = __shfl_sync(0xFFFFFFFFu, myw, src1);
        float w2 = __shfl_sync(0xFFFFFFFFu, myw, src2);
        float w3 = __shfl_sync(0xFFFFFFFFu, myw, src3);
        float w4 = __shfl_sync(0xFFFFFFFFu, myw, src4);
        float w5 = __shfl_sync(0xFFFFFFFFu, myw, src5);
        float w6 = __shfl_sync(0xFFFFFFFFu, myw, src6);
        float w7 = __shfl_sync(0xFFFFFFFFu, myw, src7);

        // 8 independent LDG.128; each covers 2 neighbor rows
        float4 v0 = e4[o0];
        float4 v1 = e4[o1];
        float4 v2 = e4[o2];
        float4 v3 = e4[o3];
        float4 v4 = e4[o4];
        float4 v5 = e4[o5];
        float4 v6 = e4[o6];
        float4 v7 = e4[o7];

        acc.x += w0 * v0.x; acc.y += w0 * v0.y; acc.z += w0 * v0.z; acc.w += w0 * v0.w;
        acc.x += w1 * v1.x; acc.y += w1 * v1.y; acc.z += w1 * v1.z; acc.w += w1 * v1.w;
        acc.x += w2 * v2.x; acc.y += w2 * v2.y; acc.z += w2 * v2.z; acc.w += w2 * v2.w;
        acc.x += w3 * v3.x; acc.y += w3 * v3.y; acc.z += w3 * v3.z; acc.w += w3 * v3.w;
        acc.x += w4 * v4.x; acc.y += w4 * v4.y; acc.z += w4 * v4.z; acc.w += w4 * v4.w;
        acc.x += w5 * v5.x; acc.y += w5 * v5.y; acc.z += w5 * v5.z; acc.w += w5 * v5.w;
        acc.x += w6 * v6.x; acc.y += w6 * v6.y; acc.z += w6 * v6.z; acc.w += w6 * v6.w;
        acc.x += w7 * v7.x; acc.y += w7 * v7.y; acc.z += w7 * v7.z; acc.w += w7 * v7.w;
    }

    // merge the two half-warp partials
    acc.x += __shfl_xor_sync(0xFFFFFFFFu, acc.x, 16);
    acc.y += __shfl_xor_sync(0xFFFFFFFFu, acc.y, 16);
    acc.z += __shfl_xor_sync(0xFFFFFFFFu, acc.z, 16);
    acc.w += __shfl_xor_sync(0xFFFFFFFFu, acc.w, 16);

    if (half == 0) {
        float4* __restrict__ o4p = reinterpret_cast<float4*>(out);
        o4p[(size_t)warp_id * (EMB/4) + hl] = acc;
    }
}

extern "C" void kernel_launch(void* const* d_in, const int* in_sizes, int n_in,
                              void* d_out, int out_size)
{
    const float* emb = (const float*)d_in[0];   // [N, 64]
    const float* wei = (const float*)d_in[1];   // [N, 32]
    const int*   nei = (const int*)d_in[2];     // [N, 32] int32
    float*       out = (float*)d_out;           // [N, 1, 64]

    const int n_nodes = in_sizes[1] / TOPK;     // 200000

    const int threads = 256;                    // 8 warps/block
    const int warps_per_block = threads / 32;
    const int blocks = (n_nodes + warps_per_block - 1) / warps_per_block;

    pprgo_kernel<<<blocks, threads>>>(emb, wei, nei, out, n_nodes);
}

// round 12
// speedup vs baseline: 1.4398x; 1.4398x over previous
#include <cuda_runtime.h>
#include <cstdint>

// PPRGo: out[n,:] = sum_k ( mask(wei[n,k]) / (sum_k mask + 1e-12) ) * emb_table[nei[n,k], :]
// N=200000, TOPK=32, EMB=64. nei is int32 on the wire.
//
// FINAL — exact R4/R10 source (88.8us best / 90.3us repro). One warp per
// node; LDG.128 covers TWO neighbor rows per instruction (lanes 0-15 ->
// row 2j, lanes 16-31 -> row 2j+1), default register budget (32 regs,
// ~88% occupancy) — at the L1tex wavefront floor (~128 phases/node
// demand+return), L2 concurrently ~77%.
// Closed axes (all regressed): cache hints (R3/R8: l1tex counts
// demand+return, policy-invariant), high-MLP via more regs (R5/R6:
// occupancy dominates), ballot-based weight math (R7/R11: perturbs ptxas's
// load batching, up to +44%), TMA/SMEM staging (R9: 2x worse).

static constexpr int TOPK = 32;
static constexpr int EMB  = 64;

__global__ __launch_bounds__(256)
void pprgo_kernel(const float* __restrict__ emb,   // [N, 64]
                  const float* __restrict__ wei,   // [N, 32]
                  const int*   __restrict__ nei,   // [N, 32] int32
                  float* __restrict__ out,         // [N, 64]
                  int n_nodes)
{
    const int warp_id = (blockIdx.x * blockDim.x + threadIdx.x) >> 5;
    const int lane    = threadIdx.x & 31;
    if (warp_id >= n_nodes) return;

    const size_t row = (size_t)warp_id * TOPK;

    // --- weight phase: lane k handles neighbor k ---
    float w  = wei[row + lane];
    float m  = (w != 0.0f) ? 1.0f : 0.0f;
    float s  = m;
    #pragma unroll
    for (int o = 16; o > 0; o >>= 1)
        s += __shfl_xor_sync(0xFFFFFFFFu, s, o);
    const float myw = m * (1.0f / (s + 1e-12f));

    const int myidx = nei[row + lane];

    // --- gather phase: half-warp h owns row 2j+h; lane covers 4 floats ---
    const int half = lane >> 4;          // 0 or 1
    const int hl   = lane & 15;          // position within half-warp

    const float4* __restrict__ e4 = reinterpret_cast<const float4*>(emb);

    float4 acc = make_float4(0.f, 0.f, 0.f, 0.f);

    #pragma unroll
    for (int j = 0; j < TOPK / 2; j += 8) {
        int src0 = 2 * (j + 0) + half;
        int src1 = 2 * (j + 1) + half;
        int src2 = 2 * (j + 2) + half;
        int src3 = 2 * (j + 3) + half;
        int src4 = 2 * (j + 4) + half;
        int src5 = 2 * (j + 5) + half;
        int src6 = 2 * (j + 6) + half;
        int src7 = 2 * (j + 7) + half;

        // 32-bit element offsets: max index 200000*16+15 < 2^32
        unsigned o0 = (unsigned)__shfl_sync(0xFFFFFFFFu, myidx, src0) * (EMB/4) + hl;
        unsigned o1 = (unsigned)__shfl_sync(0xFFFFFFFFu, myidx, src1) * (EMB/4) + hl;
        unsigned o2 = (unsigned)__shfl_sync(0xFFFFFFFFu, myidx, src2) * (EMB/4) + hl;
        unsigned o3 = (unsigned)__shfl_sync(0xFFFFFFFFu, myidx, src3) * (EMB/4) + hl;
        unsigned o4 = (unsigned)__shfl_sync(0xFFFFFFFFu, myidx, src4) * (EMB/4) + hl;
        unsigned o5 = (unsigned)__shfl_sync(0xFFFFFFFFu, myidx, src5) * (EMB/4) + hl;
        unsigned o6 = (unsigned)__shfl_sync(0xFFFFFFFFu, myidx, src6) * (EMB/4) + hl;
        unsigned o7 = (unsigned)__shfl_sync(0xFFFFFFFFu, myidx, src7) * (EMB/4) + hl;

        float w0 = __shfl_sync(0xFFFFFFFFu, myw, src0);
        float w1 = __shfl_sync(0xFFFFFFFFu, myw, src1);
        float w2 = __shfl_sync(0xFFFFFFFFu, myw, src2);
        float w3 = __shfl_sync(0xFFFFFFFFu, myw, src3);
        float w4 = __shfl_sync(0xFFFFFFFFu, myw, src4);
        float w5 = __shfl_sync(0xFFFFFFFFu, myw, src5);
        float w6 = __shfl_sync(0xFFFFFFFFu, myw, src6);
        float w7 = __shfl_sync(0xFFFFFFFFu, myw, src7);

        // 8 independent LDG.128; each covers 2 neighbor rows
        float4 v0 = e4[o0];
        float4 v1 = e4[o1];
        float4 v2 = e4[o2];
        float4 v3 = e4[o3];
        float4 v4 = e4[o4];
        float4 v5 = e4[o5];
        float4 v6 = e4[o6];
        float4 v7 = e4[o7];

        acc.x += w0 * v0.x; acc.y += w0 * v0.y; acc.z += w0 * v0.z; acc.w += w0 * v0.w;
        acc.x += w1 * v1.x; acc.y += w1 * v1.y; acc.z += w1 * v1.z; acc.w += w1 * v1.w;
        acc.x += w2 * v2.x; acc.y += w2 * v2.y; acc.z += w2 * v2.z; acc.w += w2 * v2.w;
        acc.x += w3 * v3.x; acc.y += w3 * v3.y; acc.z += w3 * v3.z; acc.w += w3 * v3.w;
        acc.x += w4 * v4.x; acc.y += w4 * v4.y; acc.z += w4 * v4.z; acc.w += w4 * v4.w;
        acc.x += w5 * v5.x; acc.y += w5 * v5.y; acc.z += w5 * v5.z; acc.w += w5 * v5.w;
        acc.x += w6 * v6.x; acc.y += w6 * v6.y; acc.z += w6 * v6.z; acc.w += w6 * v6.w;
        acc.x += w7 * v7.x; acc.y += w7 * v7.y; acc.z += w7 * v7.z; acc.w += w7 * v7.w;
    }

    // merge the two half-warp partials
    acc.x += __shfl_xor_sync(0xFFFFFFFFu, acc.x, 16);
    acc.y += __shfl_xor_sync(0xFFFFFFFFu, acc.y, 16);
    acc.z += __shfl_xor_sync(0xFFFFFFFFu, acc.z, 16);
    acc.w += __shfl_xor_sync(0xFFFFFFFFu, acc.w, 16);

    if (half == 0) {
        float4* __restrict__ o4p = reinterpret_cast<float4*>(out);
        o4p[(size_t)warp_id * (EMB/4) + hl] = acc;
    }
}

extern "C" void kernel_launch(void* const* d_in, const int* in_sizes, int n_in,
                              void* d_out, int out_size)
{
    const float* emb = (const float*)d_in[0];   // [N, 64]
    const float* wei = (const float*)d_in[1];   // [N, 32]
    const int*   nei = (const int*)d_in[2];     // [N, 32] int32
    float*       out = (float*)d_out;           // [N, 1, 64]

    const int n_nodes = in_sizes[1] / TOPK;     // 200000

    const int threads = 256;                    // 8 warps/block
    const int warps_per_block = threads / 32;
    const int blocks = (n_nodes + warps_per_block - 1) / warps_per_block;

    pprgo_kernel<<<blocks, threads>>>(emb, wei, nei, out, n_nodes);
}

// round 13
// speedup vs baseline: 1.4685x; 1.0199x over previous
#include <cuda_runtime.h>
#include <cstdint>

// PPRGo: out[n,:] = sum_k ( mask(wei[n,k]) / (sum_k mask + 1e-12) ) * emb_table[nei[n,k], :]
// N=200000, TOPK=32, EMB=64. nei is int32 on the wire.
//
// R4 kernel body, BIT-IDENTICAL SASS (same __launch_bounds__(256), same
// source): only the launch shape changes, 128 threads/block (4 warps,
// grid=50000) instead of 256/8. Finer CTA granularity packs warp slots
// tighter and smooths the end-of-kernel drain; zero risk to the fragile
// ptxas schedule (R7/R11 showed source perturbations cost up to +44%).
// Closed axes: cache hints (R3/R8), MLP-via-regs (R5/R6), ballot weights
// (R7/R11), TMA staging (R9).

static constexpr int TOPK = 32;
static constexpr int EMB  = 64;

__global__ __launch_bounds__(256)
void pprgo_kernel(const float* __restrict__ emb,   // [N, 64]
                  const float* __restrict__ wei,   // [N, 32]
                  const int*   __restrict__ nei,   // [N, 32] int32
                  float* __restrict__ out,         // [N, 64]
                  int n_nodes)
{
    const int warp_id = (blockIdx.x * blockDim.x + threadIdx.x) >> 5;
    const int lane    = threadIdx.x & 31;
    if (warp_id >= n_nodes) return;

    const size_t row = (size_t)warp_id * TOPK;

    // --- weight phase: lane k handles neighbor k ---
    float w  = wei[row + lane];
    float m  = (w != 0.0f) ? 1.0f : 0.0f;
    float s  = m;
    #pragma unroll
    for (int o = 16; o > 0; o >>= 1)
        s += __shfl_xor_sync(0xFFFFFFFFu, s, o);
    const float myw = m * (1.0f / (s + 1e-12f));

    const int myidx = nei[row + lane];

    // --- gather phase: half-warp h owns row 2j+h; lane covers 4 floats ---
    const int half = lane >> 4;          // 0 or 1
    const int hl   = lane & 15;          // position within half-warp

    const float4* __restrict__ e4 = reinterpret_cast<const float4*>(emb);

    float4 acc = make_float4(0.f, 0.f, 0.f, 0.f);

    #pragma unroll
    for (int j = 0; j < TOPK / 2; j += 8) {
        int src0 = 2 * (j + 0) + half;
        int src1 = 2 * (j + 1) + half;
        int src2 = 2 * (j + 2) + half;
        int src3 = 2 * (j + 3) + half;
        int src4 = 2 * (j + 4) + half;
        int src5 = 2 * (j + 5) + half;
        int src6 = 2 * (j + 6) + half;
        int src7 = 2 * (j + 7) + half;

        // 32-bit element offsets: max index 200000*16+15 < 2^32
        unsigned o0 = (unsigned)__shfl_sync(0xFFFFFFFFu, myidx, src0) * (EMB/4) + hl;
        unsigned o1 = (unsigned)__shfl_sync(0xFFFFFFFFu, myidx, src1) * (EMB/4) + hl;
        unsigned o2 = (unsigned)__shfl_sync(0xFFFFFFFFu, myidx, src2) * (EMB/4) + hl;
        unsigned o3 = (unsigned)__shfl_sync(0xFFFFFFFFu, myidx, src3) * (EMB/4) + hl;
        unsigned o4 = (unsigned)__shfl_sync(0xFFFFFFFFu, myidx, src4) * (EMB/4) + hl;
        unsigned o5 = (unsigned)__shfl_sync(0xFFFFFFFFu, myidx, src5) * (EMB/4) + hl;
        unsigned o6 = (unsigned)__shfl_sync(0xFFFFFFFFu, myidx, src6) * (EMB/4) + hl;
        unsigned o7 = (unsigned)__shfl_sync(0xFFFFFFFFu, myidx, src7) * (EMB/4) + hl;

        float w0 = __shfl_sync(0xFFFFFFFFu, myw, src0);
        float w1 = __shfl_sync(0xFFFFFFFFu, myw, src1);
        float w2 = __shfl_sync(0xFFFFFFFFu, myw, src2);
        float w3 = __shfl_sync(0xFFFFFFFFu, myw, src3);
        float w4 = __shfl_sync(0xFFFFFFFFu, myw, src4);
        float w5 = __shfl_sync(0xFFFFFFFFu, myw, src5);
        float w6 = __shfl_sync(0xFFFFFFFFu, myw, src6);
        float w7 = __shfl_sync(0xFFFFFFFFu, myw, src7);

        // 8 independent LDG.128; each covers 2 neighbor rows
        float4 v0 = e4[o0];
        float4 v1 = e4[o1];
        float4 v2 = e4[o2];
        float4 v3 = e4[o3];
        float4 v4 = e4[o4];
        float4 v5 = e4[o5];
        float4 v6 = e4[o6];
        float4 v7 = e4[o7];

        acc.x += w0 * v0.x; acc.y += w0 * v0.y; acc.z += w0 * v0.z; acc.w += w0 * v0.w;
        acc.x += w1 * v1.x; acc.y += w1 * v1.y; acc.z += w1 * v1.z; acc.w += w1 * v1.w;
        acc.x += w2 * v2.x; acc.y += w2 * v2.y; acc.z += w2 * v2.z; acc.w += w2 * v2.w;
        acc.x += w3 * v3.x; acc.y += w3 * v3.y; acc.z += w3 * v3.z; acc.w += w3 * v3.w;
        acc.x += w4 * v4.x; acc.y += w4 * v4.y; acc.z += w4 * v4.z; acc.w += w4 * v4.w;
        acc.x += w5 * v5.x; acc.y += w5 * v5.y; acc.z += w5 * v5.z; acc.w += w5 * v5.w;
        acc.x += w6 * v6.x; acc.y += w6 * v6.y; acc.z += w6 * v6.z; acc.w += w6 * v6.w;
        acc.x += w7 * v7.x; acc.y += w7 * v7.y; acc.z += w7 * v7.z; acc.w += w7 * v7.w;
    }

    // merge the two half-warp partials
    acc.x += __shfl_xor_sync(0xFFFFFFFFu, acc.x, 16);
    acc.y += __shfl_xor_sync(0xFFFFFFFFu, acc.y, 16);
    acc.z += __shfl_xor_sync(0xFFFFFFFFu, acc.z, 16);
    acc.w += __shfl_xor_sync(0xFFFFFFFFu, acc.w, 16);

    if (half == 0) {
        float4* __restrict__ o4p = reinterpret_cast<float4*>(out);
        o4p[(size_t)warp_id * (EMB/4) + hl] = acc;
    }
}

extern "C" void kernel_launch(void* const* d_in, const int* in_sizes, int n_in,
                              void* d_out, int out_size)
{
    const float* emb = (const float*)d_in[0];   // [N, 64]
    const float* wei = (const float*)d_in[1];   // [N, 32]
    const int*   nei = (const int*)d_in[2];     // [N, 32] int32
    float*       out = (float*)d_out;           // [N, 1, 64]

    const int n_nodes = in_sizes[1] / TOPK;     // 200000

    const int threads = 128;                    // 4 warps/block (<= launch_bounds 256)
    const int warps_per_block = threads / 32;
    const int blocks = (n_nodes + warps_per_block - 1) / warps_per_block;  // 50000

    pprgo_kernel<<<blocks, threads>>>(emb, wei, nei, out, n_nodes);
}

// round 14
// speedup vs baseline: 1.5006x; 1.0218x over previous
#include <cuda_runtime.h>
#include <cstdint>

// PPRGo: out[n,:] = sum_k ( mask(wei[n,k]) / (sum_k mask + 1e-12) ) * emb_table[nei[n,k], :]
// N=200000, TOPK=32, EMB=64. nei is int32 on the wire.
//
// R4 kernel body, BIT-IDENTICAL SASS. Launch-shape axis: 256/blk = 90.1us,
// 128/blk = 88.4us (R13 win, occ 90%). This round: 64 threads/block
// (2 warps, grid=100000) — finest CTA granularity that keeps the full
// 64-warp/SM slot count (32-CTA cap x 2 warps). Zero risk to the fragile
// ptxas schedule (R7/R11: source perturbations cost up to +44%).
// Closed axes: cache hints (R3/R8), MLP-via-regs (R5/R6), ballot weights
// (R7/R11), TMA staging (R9).

static constexpr int TOPK = 32;
static constexpr int EMB  = 64;

__global__ __launch_bounds__(256)
void pprgo_kernel(const float* __restrict__ emb,   // [N, 64]
                  const float* __restrict__ wei,   // [N, 32]
                  const int*   __restrict__ nei,   // [N, 32] int32
                  float* __restrict__ out,         // [N, 64]
                  int n_nodes)
{
    const int warp_id = (blockIdx.x * blockDim.x + threadIdx.x) >> 5;
    const int lane    = threadIdx.x & 31;
    if (warp_id >= n_nodes) return;

    const size_t row = (size_t)warp_id * TOPK;

    // --- weight phase: lane k handles neighbor k ---
    float w  = wei[row + lane];
    float m  = (w != 0.0f) ? 1.0f : 0.0f;
    float s  = m;
    #pragma unroll
    for (int o = 16; o > 0; o >>= 1)
        s += __shfl_xor_sync(0xFFFFFFFFu, s, o);
    const float myw = m * (1.0f / (s + 1e-12f));

    const int myidx = nei[row + lane];

    // --- gather phase: half-warp h owns row 2j+h; lane covers 4 floats ---
    const int half = lane >> 4;          // 0 or 1
    const int hl   = lane & 15;          // position within half-warp

    const float4* __restrict__ e4 = reinterpret_cast<const float4*>(emb);

    float4 acc = make_float4(0.f, 0.f, 0.f, 0.f);

    #pragma unroll
    for (int j = 0; j < TOPK / 2; j += 8) {
        int src0 = 2 * (j + 0) + half;
        int src1 = 2 * (j + 1) + half;
        int src2 = 2 * (j + 2) + half;
        int src3 = 2 * (j + 3) + half;
        int src4 = 2 * (j + 4) + half;
        int src5 = 2 * (j + 5) + half;
        int src6 = 2 * (j + 6) + half;
        int src7 = 2 * (j + 7) + half;

        // 32-bit element offsets: max index 200000*16+15 < 2^32
        unsigned o0 = (unsigned)__shfl_sync(0xFFFFFFFFu, myidx, src0) * (EMB/4) + hl;
        unsigned o1 = (unsigned)__shfl_sync(0xFFFFFFFFu, myidx, src1) * (EMB/4) + hl;
        unsigned o2 = (unsigned)__shfl_sync(0xFFFFFFFFu, myidx, src2) * (EMB/4) + hl;
        unsigned o3 = (unsigned)__shfl_sync(0xFFFFFFFFu, myidx, src3) * (EMB/4) + hl;
        unsigned o4 = (unsigned)__shfl_sync(0xFFFFFFFFu, myidx, src4) * (EMB/4) + hl;
        unsigned o5 = (unsigned)__shfl_sync(0xFFFFFFFFu, myidx, src5) * (EMB/4) + hl;
        unsigned o6 = (unsigned)__shfl_sync(0xFFFFFFFFu, myidx, src6) * (EMB/4) + hl;
        unsigned o7 = (unsigned)__shfl_sync(0xFFFFFFFFu, myidx, src7) * (EMB/4) + hl;

        float w0 = __shfl_sync(0xFFFFFFFFu, myw, src0);
        float w1 = __shfl_sync(0xFFFFFFFFu, myw, src1);
        float w2 = __shfl_sync(0xFFFFFFFFu, myw, src2);
        float w3 = __shfl_sync(0xFFFFFFFFu, myw, src3);
        float w4 = __shfl_sync(0xFFFFFFFFu, myw, src4);
        float w5 = __shfl_sync(0xFFFFFFFFu, myw, src5);
        float w6 = __shfl_sync(0xFFFFFFFFu, myw, src6);
        float w7 = __shfl_sync(0xFFFFFFFFu, myw, src7);

        // 8 independent LDG.128; each covers 2 neighbor rows
        float4 v0 = e4[o0];
        float4 v1 = e4[o1];
        float4 v2 = e4[o2];
        float4 v3 = e4[o3];
        float4 v4 = e4[o4];
        float4 v5 = e4[o5];
        float4 v6 = e4[o6];
        float4 v7 = e4[o7];

        acc.x += w0 * v0.x; acc.y += w0 * v0.y; acc.z += w0 * v0.z; acc.w += w0 * v0.w;
        acc.x += w1 * v1.x; acc.y += w1 * v1.y; acc.z += w1 * v1.z; acc.w += w1 * v1.w;
        acc.x += w2 * v2.x; acc.y += w2 * v2.y; acc.z += w2 * v2.z; acc.w += w2 * v2.w;
        acc.x += w3 * v3.x; acc.y += w3 * v3.y; acc.z += w3 * v3.z; acc.w += w3 * v3.w;
        acc.x += w4 * v4.x; acc.y += w4 * v4.y; acc.z += w4 * v4.z; acc.w += w4 * v4.w;
        acc.x += w5 * v5.x; acc.y += w5 * v5.y; acc.z += w5 * v5.z; acc.w += w5 * v5.w;
        acc.x += w6 * v6.x; acc.y += w6 * v6.y; acc.z += w6 * v6.z; acc.w += w6 * v6.w;
        acc.x += w7 * v7.x; acc.y += w7 * v7.y; acc.z += w7 * v7.z; acc.w += w7 * v7.w;
    }

    // merge the two half-warp partials
    acc.x += __shfl_xor_sync(0xFFFFFFFFu, acc.x, 16);
    acc.y += __shfl_xor_sync(0xFFFFFFFFu, acc.y, 16);
    acc.z += __shfl_xor_sync(0xFFFFFFFFu, acc.z, 16);
    acc.w += __shfl_xor_sync(0xFFFFFFFFu, acc.w, 16);

    if (half == 0) {
        float4* __restrict__ o4p = reinterpret_cast<float4*>(out);
        o4p[(size_t)warp_id * (EMB/4) + hl] = acc;
    }
}

extern "C" void kernel_launch(void* const* d_in, const int* in_sizes, int n_in,
                              void* d_out, int out_size)
{
    const float* emb = (const float*)d_in[0];   // [N, 64]
    const float* wei = (const float*)d_in[1];   // [N, 32]
    const int*   nei = (const int*)d_in[2];     // [N, 32] int32
    float*       out = (float*)d_out;           // [N, 1, 64]

    const int n_nodes = in_sizes[1] / TOPK;     // 200000

    const int threads = 64;                     // 2 warps/block
    const int warps_per_block = threads / 32;
    const int blocks = (n_nodes + warps_per_block - 1) / warps_per_block;  // 100000

    pprgo_kernel<<<blocks, threads>>>(emb, wei, nei, out, n_nodes);
}